// round 5
// baseline (speedup 1.0000x reference)
#include <cuda_runtime.h>
#include <cstdint>

// Haar-DWT L1 loss, B=32,C=1,H=512,W=512 fp32 x2 inputs.
// DWT is linear -> butterfly the per-pixel diff.
// Row-pair (rows 2r,2r+1) = 1024 contiguous floats = 4KB per tensor.
// Total row-pairs N_RP = 32*256 = 8192; Haar blocks = 8192*256 = 2,097,152.
#define N_RP           8192
#define N_BLOCKS_TOTAL 2097152.0f

#define CTAS    608      // 152 SMs * 4 CTAs, one balanced wave
#define THREADS 128
#define NSTAGE  4
#define RP_FLOATS 1024   // floats per row-pair per tensor
#define RP_BYTES  4096
#define STAGE_TX  (2 * RP_BYTES)   // in + tgt per stage

__global__ void zero_out_kernel(float* out) {
    if (threadIdx.x < 2) out[threadIdx.x] = 0.0f;
}

// ---- mbarrier / bulk-copy PTX helpers ----
__device__ __forceinline__ uint32_t smem_u32(const void* p) {
    return (uint32_t)__cvta_generic_to_shared(p);
}
__device__ __forceinline__ void mbar_init(uint32_t mbar, uint32_t count) {
    asm volatile("mbarrier.init.shared.b64 [%0], %1;" :: "r"(mbar), "r"(count) : "memory");
}
__device__ __forceinline__ void mbar_expect_tx(uint32_t mbar, uint32_t bytes) {
    asm volatile("mbarrier.arrive.expect_tx.shared.b64 _, [%0], %1;"
                 :: "r"(mbar), "r"(bytes) : "memory");
}
__device__ __forceinline__ void mbar_arrive(uint32_t mbar) {
    asm volatile("mbarrier.arrive.shared.b64 _, [%0];" :: "r"(mbar) : "memory");
}
__device__ __forceinline__ void mbar_wait(uint32_t mbar, uint32_t parity) {
    asm volatile(
        "{\n\t.reg .pred P;\n\t"
        "WL_%=:\n\t"
        "mbarrier.try_wait.parity.acquire.cta.shared::cta.b64 P, [%0], %1, 0x989680;\n\t"
        "@!P bra WL_%=;\n\t}"
        :: "r"(mbar), "r"(parity) : "memory");
}
__device__ __forceinline__ void bulk_g2s(uint32_t dst, const void* src,
                                         uint32_t bytes, uint32_t mbar) {
    asm volatile(
        "cp.async.bulk.shared::cta.global.mbarrier::complete_tx::bytes "
        "[%0], [%1], %2, [%3];"
        :: "r"(dst), "l"(src), "r"(bytes), "r"(mbar) : "memory");
}

__device__ __forceinline__ void haar_accum(
    const float4& i0, const float4& i1, const float4& t0, const float4& t1,
    float& lo, float& hi)
{
    // diffs: row0 = (a0,b0,a1,b1), row1 = (c0,d0,c1,d1)
    const float da0 = i0.x - t0.x, db0 = i0.y - t0.y;
    const float da1 = i0.z - t0.z, db1 = i0.w - t0.w;
    const float dc0 = i1.x - t1.x, dd0 = i1.y - t1.y;
    const float dc1 = i1.z - t1.z, dd1 = i1.w - t1.w;
    // Haar butterfly on diff (0.5 folded into final scale)
    {
        const float p = da0 + db0, qq = dc0 + dd0;
        const float u = da0 - db0, v  = dc0 - dd0;
        lo += fabsf(p + qq);
        hi += fabsf(qq - p) + fabsf(u + v) + fabsf(u - v);
    }
    {
        const float p = da1 + db1, qq = dc1 + dd1;
        const float u = da1 - db1, v  = dc1 - dd1;
        lo += fabsf(p + qq);
        hi += fabsf(qq - p) + fabsf(u + v) + fabsf(u - v);
    }
}

__global__ __launch_bounds__(THREADS) void haar_loss_kernel(
    const float* __restrict__ in,
    const float* __restrict__ tgt,
    float* __restrict__ out)
{
    __shared__ alignas(1024) float s_in[NSTAGE][RP_FLOATS];
    __shared__ alignas(1024) float s_tg[NSTAGE][RP_FLOATS];
    __shared__ alignas(8) uint64_t s_full_mem[NSTAGE];
    __shared__ alignas(8) uint64_t s_empty_mem[NSTAGE];

    const int tid = threadIdx.x;
    const int bid = blockIdx.x;

    uint32_t full_b[NSTAGE], empty_b[NSTAGE], in_b[NSTAGE], tg_b[NSTAGE];
    #pragma unroll
    for (int s = 0; s < NSTAGE; s++) {
        full_b[s]  = smem_u32(&s_full_mem[s]);
        empty_b[s] = smem_u32(&s_empty_mem[s]);
        in_b[s]    = smem_u32(&s_in[s][0]);
        tg_b[s]    = smem_u32(&s_tg[s][0]);
    }

    // 8192 = 13*608 + 288 -> first 288 CTAs do 14 row-pairs, rest 13
    const int trips = 13 + (bid < 288 ? 1 : 0);

    if (tid == 0) {
        #pragma unroll
        for (int s = 0; s < NSTAGE; s++) {
            mbar_init(full_b[s], 1);          // expect_tx arrives once per phase
            mbar_init(empty_b[s], THREADS);   // all consumers arrive
        }
    }
    __syncthreads();

    // Prefill all NSTAGE stages (fresh barriers, no empty wait needed).
    if (tid == 0) {
        #pragma unroll
        for (int f = 0; f < NSTAGE; f++) {
            const int rp = bid + f * CTAS;
            mbar_expect_tx(full_b[f], STAGE_TX);
            bulk_g2s(in_b[f], in  + (size_t)rp * RP_FLOATS, RP_BYTES, full_b[f]);
            bulk_g2s(tg_b[f], tgt + (size_t)rp * RP_FLOATS, RP_BYTES, full_b[f]);
        }
    }

    float lo = 0.0f, hi = 0.0f;

    for (int i = 0; i < trips; i++) {
        const int s  = i & (NSTAGE - 1);
        const uint32_t ph = (i >> 2) & 1;

        mbar_wait(full_b[s], ph);

        const float4* pi = (const float4*)&s_in[s][0];
        const float4* pt = (const float4*)&s_tg[s][0];
        const float4 i0 = pi[tid];
        const float4 i1 = pi[tid + 128];
        const float4 t0 = pt[tid];
        const float4 t1 = pt[tid + 128];
        haar_accum(i0, i1, t0, t1, lo, hi);

        mbar_arrive(empty_b[s]);

        // Refill this stage for iteration i+NSTAGE (producer thread only).
        if (tid == 0 && i + NSTAGE < trips) {
            mbar_wait(empty_b[s], ph);  // wait for all 128 arrivals of iter i
            const int rp = bid + (i + NSTAGE) * CTAS;
            mbar_expect_tx(full_b[s], STAGE_TX);
            bulk_g2s(in_b[s], in  + (size_t)rp * RP_FLOATS, RP_BYTES, full_b[s]);
            bulk_g2s(tg_b[s], tgt + (size_t)rp * RP_FLOATS, RP_BYTES, full_b[s]);
        }
    }

    // ---- block reduce + atomic epilogue ----
    #pragma unroll
    for (int o = 16; o > 0; o >>= 1) {
        lo += __shfl_xor_sync(0xffffffffu, lo, o);
        hi += __shfl_xor_sync(0xffffffffu, hi, o);
    }
    __shared__ float slo[THREADS / 32], shi[THREADS / 32];
    const int warp = tid >> 5;
    const int lane = tid & 31;
    if (lane == 0) { slo[warp] = lo; shi[warp] = hi; }
    __syncthreads();
    if (tid < 32) {
        lo = (lane < THREADS / 32) ? slo[lane] : 0.0f;
        hi = (lane < THREADS / 32) ? shi[lane] : 0.0f;
        #pragma unroll
        for (int o = 2; o > 0; o >>= 1) {
            lo += __shfl_xor_sync(0xffffffffu, lo, o);
            hi += __shfl_xor_sync(0xffffffffu, hi, o);
        }
        if (lane == 0) {
            const float sL = 0.5f / N_BLOCKS_TOTAL;
            const float sH = 0.5f / (3.0f * N_BLOCKS_TOTAL);
            atomicAdd(&out[0], lo * sL);
            atomicAdd(&out[1], hi * sH);
        }
    }
}

extern "C" void kernel_launch(void* const* d_in, const int* in_sizes, int n_in,
                              void* d_out, int out_size) {
    const float* in  = (const float*)d_in[0];
    const float* tgt = (const float*)d_in[1];
    float* out = (float*)d_out;

    zero_out_kernel<<<1, 32>>>(out);
    haar_loss_kernel<<<CTAS, THREADS>>>(in, tgt, out);
}

// round 6
// speedup vs baseline: 1.2850x; 1.2850x over previous
#include <cuda_runtime.h>

// Haar-DWT L1 loss, B=32,C=1,H=512,W=512 fp32 x2 inputs.
// DWT is linear -> butterfly the per-pixel diff. One "quad-pair" = float4 from
// row 2r + the float4 below it in row 2r+1 (both tensors) = 2 Haar blocks.
// N_QUADS = 32*256*128 = 1,048,576. Total Haar blocks = 2,097,152.
#define N_BLOCKS_TOTAL 2097152.0f

#define CTAS    512
#define THREADS 256
#define PAIRS   8
#define STRIDE  (CTAS * THREADS)   // 131072; CTAS*THREADS*PAIRS == N_QUADS exactly

// Cross-CTA accumulation scratch (zero at module load; reset by last CTA each
// run so graph replays stay correct).
__device__ float        g_acc[2] = {0.0f, 0.0f};
__device__ unsigned int g_count  = 0;

__device__ __forceinline__ void load_pair(
    const float4* __restrict__ in, const float4* __restrict__ tgt, int p,
    float4& i0, float4& i1, float4& t0, float4& t1)
{
    // quad p -> row-pair grp = p>>7, col c4 = p&127; base0 = grp*256 + c4
    const int c4    = p & 127;
    const int base0 = 2 * p - c4;
    const int base1 = base0 + 128;
    i0 = in[base0];
    i1 = in[base1];
    t0 = tgt[base0];
    t1 = tgt[base1];
}

__device__ __forceinline__ void haar_accum(
    const float4& i0, const float4& i1, const float4& t0, const float4& t1,
    float& lo, float& hi)
{
    // diffs: row0 = (a0,b0,a1,b1), row1 = (c0,d0,c1,d1)
    const float da0 = i0.x - t0.x, db0 = i0.y - t0.y;
    const float da1 = i0.z - t0.z, db1 = i0.w - t0.w;
    const float dc0 = i1.x - t1.x, dd0 = i1.y - t1.y;
    const float dc1 = i1.z - t1.z, dd1 = i1.w - t1.w;

    // Haar butterfly on diff (0.5 folded into final scale):
    // 2*ll = p+q, 2*lh = q-p, 2*hl = -(u+v), 2*hh = u-v
    {
        const float p = da0 + db0, qq = dc0 + dd0;
        const float u = da0 - db0, v  = dc0 - dd0;
        lo += fabsf(p + qq);
        hi += fabsf(qq - p) + fabsf(u + v) + fabsf(u - v);
    }
    {
        const float p = da1 + db1, qq = dc1 + dd1;
        const float u = da1 - db1, v  = dc1 - dd1;
        lo += fabsf(p + qq);
        hi += fabsf(qq - p) + fabsf(u + v) + fabsf(u - v);
    }
}

__global__ __launch_bounds__(THREADS, 4) void haar_loss_kernel(
    const float4* __restrict__ in,
    const float4* __restrict__ tgt,
    float* __restrict__ out)
{
    const int q0 = blockIdx.x * THREADS + threadIdx.x;

    float lo = 0.0f, hi = 0.0f;

    // 2-deep software pipeline over PAIRS fully-unrolled iterations:
    // batch j+1's 4 LDG.128 in flight while computing batch j. No predicates.
    float4 ci0, ci1, ct0, ct1;
    load_pair(in, tgt, q0, ci0, ci1, ct0, ct1);

    #pragma unroll
    for (int j = 0; j < PAIRS; j++) {
        float4 ni0, ni1, nt0, nt1;
        if (j + 1 < PAIRS) {
            load_pair(in, tgt, q0 + (j + 1) * STRIDE, ni0, ni1, nt0, nt1);
        }
        haar_accum(ci0, ci1, ct0, ct1, lo, hi);
        if (j + 1 < PAIRS) {
            ci0 = ni0; ci1 = ni1; ct0 = nt0; ct1 = nt1;
        }
    }

    // warp reduction
    #pragma unroll
    for (int o = 16; o > 0; o >>= 1) {
        lo += __shfl_xor_sync(0xffffffffu, lo, o);
        hi += __shfl_xor_sync(0xffffffffu, hi, o);
    }

    __shared__ float slo[THREADS / 32], shi[THREADS / 32];
    const int warp = threadIdx.x >> 5;
    const int lane = threadIdx.x & 31;
    if (lane == 0) { slo[warp] = lo; shi[warp] = hi; }
    __syncthreads();

    if (threadIdx.x == 0) {
        lo = 0.0f; hi = 0.0f;
        #pragma unroll
        for (int w = 0; w < THREADS / 32; w++) { lo += slo[w]; hi += shi[w]; }

        // accumulate into device globals; last CTA finalizes (O(1) tail)
        atomicAdd(&g_acc[0], lo);
        atomicAdd(&g_acc[1], hi);
        __threadfence();
        const unsigned int c = atomicAdd(&g_count, 1u);
        if (c == CTAS - 1) {
            __threadfence();  // acquire: see all CTAs' accumulations
            const float sL = 0.5f / N_BLOCKS_TOTAL;
            const float sH = 0.5f / (3.0f * N_BLOCKS_TOTAL);
            out[0] = g_acc[0] * sL;
            out[1] = g_acc[1] * sH;
            // reset for next graph replay
            g_acc[0] = 0.0f;
            g_acc[1] = 0.0f;
            __threadfence();
            g_count = 0;
        }
    }
}

extern "C" void kernel_launch(void* const* d_in, const int* in_sizes, int n_in,
                              void* d_out, int out_size) {
    const float4* in  = (const float4*)d_in[0];
    const float4* tgt = (const float4*)d_in[1];
    float* out = (float*)d_out;

    haar_loss_kernel<<<CTAS, THREADS>>>(in, tgt, out);
}

// round 7
// speedup vs baseline: 1.5298x; 1.1905x over previous
#include <cuda_runtime.h>

// Haar-DWT L1 loss, B=32,C=1,H=512,W=512 fp32 x2 inputs.
// DWT is linear -> butterfly the per-pixel diff. One "quad-pair" = float4 from
// row 2r + the float4 below it in row 2r+1 (both tensors) = 2 Haar blocks.
// N_QUADS = 32*256*128 = 1,048,576. Total Haar blocks = 2,097,152.
#define N_BLOCKS_TOTAL 2097152.0f

#define CTAS    512
#define THREADS 256
#define PAIRS   8
#define STRIDE  (CTAS * THREADS)   // 131072; CTAS*THREADS*PAIRS == N_QUADS exactly

__global__ void zero_out_kernel(float* out) {
    if (threadIdx.x < 2) out[threadIdx.x] = 0.0f;
}

__device__ __forceinline__ void load_pair(
    const float4* __restrict__ in, const float4* __restrict__ tgt, int p,
    float4& i0, float4& i1, float4& t0, float4& t1)
{
    // quad p -> row-pair grp = p>>7, col c4 = p&127; base0 = grp*256 + c4
    const int c4    = p & 127;
    const int base0 = 2 * p - c4;
    const int base1 = base0 + 128;
    // Streaming loads: zero reuse, keep L2 from thrashing on the 134MB stream.
    i0 = __ldcs(&in[base0]);
    i1 = __ldcs(&in[base1]);
    t0 = __ldcs(&tgt[base0]);
    t1 = __ldcs(&tgt[base1]);
}

__device__ __forceinline__ void haar_accum(
    const float4& i0, const float4& i1, const float4& t0, const float4& t1,
    float& lo, float& hi)
{
    // diffs: row0 = (a0,b0,a1,b1), row1 = (c0,d0,c1,d1)
    const float da0 = i0.x - t0.x, db0 = i0.y - t0.y;
    const float da1 = i0.z - t0.z, db1 = i0.w - t0.w;
    const float dc0 = i1.x - t1.x, dd0 = i1.y - t1.y;
    const float dc1 = i1.z - t1.z, dd1 = i1.w - t1.w;

    // Haar butterfly on diff (0.5 folded into final scale):
    // 2*ll = p+q, 2*lh = q-p, 2*hl = -(u+v), 2*hh = u-v
    {
        const float p = da0 + db0, qq = dc0 + dd0;
        const float u = da0 - db0, v  = dc0 - dd0;
        lo += fabsf(p + qq);
        hi += fabsf(qq - p) + fabsf(u + v) + fabsf(u - v);
    }
    {
        const float p = da1 + db1, qq = dc1 + dd1;
        const float u = da1 - db1, v  = dc1 - dd1;
        lo += fabsf(p + qq);
        hi += fabsf(qq - p) + fabsf(u + v) + fabsf(u - v);
    }
}

__global__ __launch_bounds__(THREADS, 4) void haar_loss_kernel(
    const float4* __restrict__ in,
    const float4* __restrict__ tgt,
    float* __restrict__ out)
{
    const int q0 = blockIdx.x * THREADS + threadIdx.x;

    float lo = 0.0f, hi = 0.0f;

    // 2-deep software pipeline over PAIRS fully-unrolled iterations:
    // batch j+1's 4 LDG.128 in flight while computing batch j. No predicates.
    float4 ci0, ci1, ct0, ct1;
    load_pair(in, tgt, q0, ci0, ci1, ct0, ct1);

    #pragma unroll
    for (int j = 0; j < PAIRS; j++) {
        float4 ni0, ni1, nt0, nt1;
        if (j + 1 < PAIRS) {
            load_pair(in, tgt, q0 + (j + 1) * STRIDE, ni0, ni1, nt0, nt1);
        }
        haar_accum(ci0, ci1, ct0, ct1, lo, hi);
        if (j + 1 < PAIRS) {
            ci0 = ni0; ci1 = ni1; ct0 = nt0; ct1 = nt1;
        }
    }

    // warp reduction
    #pragma unroll
    for (int o = 16; o > 0; o >>= 1) {
        lo += __shfl_xor_sync(0xffffffffu, lo, o);
        hi += __shfl_xor_sync(0xffffffffu, hi, o);
    }

    __shared__ float slo[THREADS / 32], shi[THREADS / 32];
    const int warp = threadIdx.x >> 5;
    const int lane = threadIdx.x & 31;
    if (lane == 0) { slo[warp] = lo; shi[warp] = hi; }
    __syncthreads();

    if (threadIdx.x < 32) {
        lo = (lane < THREADS / 32) ? slo[lane] : 0.0f;
        hi = (lane < THREADS / 32) ? shi[lane] : 0.0f;
        #pragma unroll
        for (int o = 4; o > 0; o >>= 1) {
            lo += __shfl_xor_sync(0xffffffffu, lo, o);
            hi += __shfl_xor_sync(0xffffffffu, hi, o);
        }
        if (lane == 0) {
            const float sL = 0.5f / N_BLOCKS_TOTAL;
            const float sH = 0.5f / (3.0f * N_BLOCKS_TOTAL);
            atomicAdd(&out[0], lo * sL);
            atomicAdd(&out[1], hi * sH);
        }
    }
}

extern "C" void kernel_launch(void* const* d_in, const int* in_sizes, int n_in,
                              void* d_out, int out_size) {
    const float4* in  = (const float4*)d_in[0];
    const float4* tgt = (const float4*)d_in[1];
    float* out = (float*)d_out;

    zero_out_kernel<<<1, 32>>>(out);
    haar_loss_kernel<<<CTAS, THREADS>>>(in, tgt, out);
}